// round 16
// baseline (speedup 1.0000x reference)
#include <cuda_runtime.h>
#include <cuda_fp16.h>
#include <math.h>

// ---------------- problem constants ----------------
#define B_   4
#define F_   256
#define N0_  128
#define N_   256
#define BN_  1024
#define L_   3
#define GRID 128

#define KW  20     // 32-bit words per 32-half smem row (16 data + 4 pad)
#define ALW 132    // 32-bit words per 256-half alpha row

// ---------------- scratch ----------------
__device__ float  g_x[BN_ * F_];
__device__ __half g_xh[BN_ * F_];
__device__ __half g_Hh[2 * F_ * BN_];     // H transposed: [r][e][node]
__device__ __half g_Wh[L_ * 2 * F_ * F_]; // conv W transposed
__device__ __half g_lwh[L_ * F_ * 2 * F_];
__device__ __half g_m1h[BN_ * F_];
__device__ float  g_msg2[BN_ * F_];
__device__ float  g_qs[2 * BN_], g_ks[2 * BN_];
__device__ float  g_sum[F_], g_sum2[F_];
__device__ unsigned g_barc[16];
__device__ unsigned g_donec;

// ---------------- helpers ----------------
__device__ __forceinline__ void mma16(float* d, const unsigned* a, const unsigned* b) {
    asm volatile(
        "mma.sync.aligned.m16n8k16.row.col.f32.f16.f16.f32 "
        "{%0,%1,%2,%3},{%4,%5,%6,%7},{%8,%9},{%0,%1,%2,%3};\n"
        : "+f"(d[0]), "+f"(d[1]), "+f"(d[2]), "+f"(d[3])
        : "r"(a[0]), "r"(a[1]), "r"(a[2]), "r"(a[3]), "r"(b[0]), "r"(b[1]));
}

__device__ __forceinline__ void cpa16h(__half* s, const __half* g) {
    unsigned ss = (unsigned)__cvta_generic_to_shared(s);
    asm volatile("cp.async.cg.shared.global [%0], [%1], 16;\n" :: "r"(ss), "l"(g));
}
#define CP_COMMIT() asm volatile("cp.async.commit_group;\n")
#define CP_WAIT1()  asm volatile("cp.async.wait_group 1;\n")

// grid barrier: release arrive, acquire poll. All GRID blocks co-resident.
__device__ __forceinline__ void gbar(int idx) {
    __syncthreads();
    if (threadIdx.x == 0) {
        unsigned dummy;
        asm volatile("atom.add.release.gpu.u32 %0, [%1], 1;"
                     : "=r"(dummy) : "l"(&g_barc[idx]) : "memory");
        unsigned v;
        do {
            asm volatile("ld.acquire.gpu.u32 %0, [%1];" : "=r"(v) : "l"(&g_barc[idx]) : "memory");
        } while (v < GRID);
    }
    __syncthreads();
}

// ---------------- phase bodies ----------------
__device__ void prep_body(int bid, unsigned char* RAW,
                          const float* __restrict__ d0, const float* __restrict__ d1,
                          const float* __restrict__ cw, const float* __restrict__ lw) {
    int t = threadIdx.x;
    if (bid < 1024) {
        int b = bid >> 8, n = bid & 255;
        float v = (n < N0_) ? d0[(b * F_ + t) * N0_ + n]
                            : d1[(b * F_ + t) * N0_ + (n - N0_)];
        int idx = (b * N_ + n) * F_ + t;
        g_x[idx] = v;
        g_xh[idx] = __float2half_rn(v);
        if (bid < 18) {
            int zi = bid * 256 + t;
            if (zi < 2048)       g_qs[zi] = 0.f;
            else if (zi < 4096)  g_ks[zi - 2048] = 0.f;
            else if (zi < 4352)  g_sum[zi - 4096] = 0.f;
            else                 g_sum2[zi - 4352] = 0.f;
        }
    } else if (bid < 1408) {
        float* s = (float*)RAW;  // 32x33
        int tt = bid - 1024, mat = tt >> 6, tile = tt & 63;
        int fr = (tile >> 3) * 32, ec = (tile & 7) * 32;
        int tx = t & 31, ty = t >> 5;
        for (int i = ty; i < 32; i += 8) s[i * 33 + tx] = cw[(mat * F_ + fr + i) * F_ + ec + tx];
        __syncthreads();
        for (int i = ty; i < 32; i += 8)
            g_Wh[((size_t)mat * F_ + ec + i) * F_ + fr + tx] = __float2half_rn(s[tx * 33 + i]);
    } else {
        size_t i0 = (size_t)(bid - 1408) * 512 + t;
        g_lwh[i0] = __float2half_rn(lw[i0]);
        g_lwh[i0 + 256] = __float2half_rn(lw[i0 + 256]);
    }
}

// gemm_H: 128 vblocks = (4 x, 16 y, 2 r). block 64x64, 2 K-groups x 4 warps (32x32)
__device__ void gemm_body(int vb, int layer, const float* __restrict__ q,
                          const float* __restrict__ kvec, unsigned char* RAW) {
    int r = vb >> 6;
    int m0 = ((vb >> 2) & 15) * 64, n0 = (vb & 3) * 64;
    int t = threadIdx.x, lane = t & 31, warp = t >> 5;
    int kh = warp >> 2, wq = warp & 3;
    int wm = (wq >> 1) * 32, wn = (wq & 1) * 32;
    int g = lane >> 2, tg = lane & 3;
    const __half* Wp = g_Wh + (size_t)(layer * 2 + r) * F_ * F_;

    if (vb == 0) {
        for (int i = t; i < F_; i += 256) { g_sum[i] = 0.f; g_sum2[i] = 0.f; }
    }

    auto stA = [&](int s, int h) { return (__half*)(RAW + s * 20480 + h * 5120); };
    auto stB = [&](int s, int h) { return (__half*)(RAW + s * 20480 + 10240 + h * 5120); };
    auto loadst = [&](int s, int k0) {
#pragma unroll
        for (int u = 0; u < 2; u++) {
            int idx = t + u * 256;
            int h = idx >> 8, rr = (idx >> 2) & 63, seg = idx & 3;
            cpa16h(stA(s, h) + rr * (KW * 2) + seg * 8, &g_xh[(m0 + rr) * F_ + k0 + h * 32 + seg * 8]);
        }
#pragma unroll
        for (int u = 0; u < 2; u++) {
            int idx = t + u * 256;
            int h = idx >> 8, rr = (idx >> 2) & 63, seg = idx & 3;
            cpa16h(stB(s, h) + rr * (KW * 2) + seg * 8, &Wp[(n0 + rr) * F_ + k0 + h * 32 + seg * 8]);
        }
        CP_COMMIT();
    };

    float acc[2][4][4] = {};
    loadst(0, 0);
    loadst(1, 64);
    for (int i = 0; i < 4; i++) {
        CP_WAIT1();
        __syncthreads();
        const unsigned* Aw = (const unsigned*)stA(i % 3, kh);
        const unsigned* Bw = (const unsigned*)stB(i % 3, kh);
#pragma unroll
        for (int ks = 0; ks < 2; ks++) {
            int kw = ks * 8;
            unsigned a[2][4];
#pragma unroll
            for (int i2 = 0; i2 < 2; i2++) {
                int rb = wm + i2 * 16;
                a[i2][0] = Aw[(rb + g) * KW + kw + tg];
                a[i2][1] = Aw[(rb + g + 8) * KW + kw + tg];
                a[i2][2] = Aw[(rb + g) * KW + kw + tg + 4];
                a[i2][3] = Aw[(rb + g + 8) * KW + kw + tg + 4];
            }
#pragma unroll
            for (int j = 0; j < 4; j++) {
                unsigned b[2];
                b[0] = Bw[(wn + j * 8 + g) * KW + kw + tg];
                b[1] = Bw[(wn + j * 8 + g) * KW + kw + tg + 4];
                mma16(acc[0][j], a[0], b);
                mma16(acc[1][j], a[1], b);
            }
        }
        if (i + 2 < 4) loadst((i + 2) % 3, (i + 2) * 64);
        else CP_COMMIT();
    }

    __syncthreads();
    float* red = (float*)RAW;
    if (kh == 1) {
        float* p = red + (wq * 32 + lane) * 32;
#pragma unroll
        for (int i2 = 0; i2 < 2; i2++)
#pragma unroll
            for (int j = 0; j < 4; j++)
#pragma unroll
                for (int e = 0; e < 4; e++) p[i2 * 16 + j * 4 + e] = acc[i2][j][e];
    }
    __syncthreads();
    if (kh == 0) {
        const float* p = red + (wq * 32 + lane) * 32;
#pragma unroll
        for (int i2 = 0; i2 < 2; i2++)
#pragma unroll
            for (int j = 0; j < 4; j++)
#pragma unroll
                for (int e = 0; e < 4; e++) acc[i2][j][e] += p[i2 * 16 + j * 4 + e];

        float qp[2][2] = {}, kp[2][2] = {};
#pragma unroll
        for (int i2 = 0; i2 < 2; i2++)
#pragma unroll
            for (int j = 0; j < 4; j++) {
                int col = n0 + wn + j * 8 + tg * 2;
                float2 qv = *(const float2*)&q[col];
                float2 kv = *(const float2*)&kvec[col];
                qp[i2][0] += acc[i2][j][0] * qv.x + acc[i2][j][1] * qv.y;
                qp[i2][1] += acc[i2][j][2] * qv.x + acc[i2][j][3] * qv.y;
                kp[i2][0] += acc[i2][j][0] * kv.x + acc[i2][j][1] * kv.y;
                kp[i2][1] += acc[i2][j][2] * kv.x + acc[i2][j][3] * kv.y;
            }
#pragma unroll
        for (int o = 1; o < 4; o <<= 1)
#pragma unroll
            for (int i2 = 0; i2 < 2; i2++)
#pragma unroll
                for (int h = 0; h < 2; h++) {
                    qp[i2][h] += __shfl_xor_sync(0xffffffffu, qp[i2][h], o);
                    kp[i2][h] += __shfl_xor_sync(0xffffffffu, kp[i2][h], o);
                }
        if (tg == 0) {
#pragma unroll
            for (int i2 = 0; i2 < 2; i2++)
#pragma unroll
                for (int h = 0; h < 2; h++) {
                    int row = m0 + wm + i2 * 16 + g + h * 8;
                    atomicAdd(&g_qs[r * BN_ + row], qp[i2][h]);
                    atomicAdd(&g_ks[r * BN_ + row], kp[i2][h]);
                }
        }
    }
    __syncthreads();
    __half* T = (__half*)(RAW + 16384);
    if (kh == 0) {
#pragma unroll
        for (int i2 = 0; i2 < 2; i2++)
#pragma unroll
            for (int j = 0; j < 4; j++) {
                int cl = wn + j * 8 + tg * 2, rl = wm + i2 * 16 + g;
                T[cl * 80 + rl] = __float2half_rn(acc[i2][j][0]);
                T[(cl + 1) * 80 + rl] = __float2half_rn(acc[i2][j][1]);
                T[cl * 80 + rl + 8] = __float2half_rn(acc[i2][j][2]);
                T[(cl + 1) * 80 + rl + 8] = __float2half_rn(acc[i2][j][3]);
            }
    }
    __syncthreads();
    size_t base = ((size_t)r * F_ + n0) * BN_ + m0;
#pragma unroll
    for (int u = 0; u < 2; u++) {
        int idx = t + u * 256;
        int row = idx >> 3, seg = idx & 7;
        *(uint4*)&g_Hh[base + (size_t)row * BN_ + seg * 8] = *(const uint4*)&T[row * 80 + seg * 8];
    }
}

// attn: 128 vblocks = (4 x, 4 y, 8 z). block 32x64, 2 K-groups x 4 warps (16x32)
__device__ void attn_body(int vb, const float* __restrict__ convb, unsigned char* RAW) {
    int z = vb >> 4, gg = z >> 1, dc = z & 1;
    int m0c = ((vb >> 2) & 3) * 32, n0 = (vb & 3) * 64;
    __half* AL = (__half*)RAW;                       // 32*264 halves = 16896B
    unsigned char* RAWB = RAW + 16896;               // 3*10240 = 30720B
    int t = threadIdx.x, lane = t & 31, warp = t >> 5;
    int kh = warp >> 2, wq = warp & 3;
    int wm = (wq >> 1) * 16, wn = (wq & 1) * 32;
    int g = lane >> 2, tg = lane & 3;

    auto stB = [&](int s, int h) { return (__half*)(RAWB + s * 10240 + h * 5120); };
    auto loadB = [&](int s, int k0) {
        int rel = (k0 >> 7) ^ dc;
        const __half* src = g_Hh + ((size_t)rel * F_ + n0) * BN_ + gg * N_ + k0;
#pragma unroll
        for (int u = 0; u < 2; u++) {
            int idx = t + u * 256;
            int h = idx >> 8, rr = (idx >> 2) & 63, seg = idx & 3;
            cpa16h(stB(s, h) + rr * (KW * 2) + seg * 8, &src[(size_t)rr * BN_ + h * 32 + seg * 8]);
        }
        CP_COMMIT();
    };
    loadB(0, 0);
    loadB(1, 64);

#pragma unroll
    for (int rr = 0; rr < 4; rr++) {
        int rl = warp * 4 + rr;
        int d = dc * 128 + m0c + rl;
        int nd = gg * N_ + d;
        float qs0 = g_qs[nd];
        float qs1 = g_qs[BN_ + nd];
        float l[8];
        float mx = -INFINITY;
#pragma unroll
        for (int j = 0; j < 8; j++) {
            int s = j * 32 + lane;
            int rel = (s >> 7) ^ dc;
            float ksv = g_ks[rel * BN_ + gg * N_ + s];
            float qv = rel ? qs1 : qs0;
            float v = qv + ksv;
            v = v >= 0.0f ? v : 0.2f * v;
            if (s == d) v = -INFINITY;
            l[j] = v;
            mx = fmaxf(mx, v);
        }
#pragma unroll
        for (int o = 16; o; o >>= 1) mx = fmaxf(mx, __shfl_xor_sync(0xffffffffu, mx, o));
        float sum = 0.0f;
#pragma unroll
        for (int j = 0; j < 8; j++) { l[j] = expf(l[j] - mx); sum += l[j]; }
#pragma unroll
        for (int o = 16; o; o >>= 1) sum += __shfl_xor_sync(0xffffffffu, sum, o);
        float inv = 1.0f / (sum + 1e-16f);
#pragma unroll
        for (int j = 0; j < 8; j++) AL[rl * 264 + j * 32 + lane] = __float2half_rn(l[j] * inv);
    }

    float acc[4][4] = {};
    const unsigned* ALw = (const unsigned*)AL;
    for (int i = 0; i < 4; i++) {
        CP_WAIT1();
        __syncthreads();
        const unsigned* Bw = (const unsigned*)stB(i % 3, kh);
#pragma unroll
        for (int ks = 0; ks < 2; ks++) {
            int kwA = i * 32 + kh * 16 + ks * 8, kwB = ks * 8;
            unsigned a[4];
            a[0] = ALw[(wm + g) * ALW + kwA + tg];
            a[1] = ALw[(wm + g + 8) * ALW + kwA + tg];
            a[2] = ALw[(wm + g) * ALW + kwA + tg + 4];
            a[3] = ALw[(wm + g + 8) * ALW + kwA + tg + 4];
#pragma unroll
            for (int j = 0; j < 4; j++) {
                unsigned b[2];
                b[0] = Bw[(wn + j * 8 + g) * KW + kwB + tg];
                b[1] = Bw[(wn + j * 8 + g) * KW + kwB + tg + 4];
                mma16(acc[j], a, b);
            }
        }
        if (i + 2 < 4) loadB((i + 2) % 3, (i + 2) * 64);
        else CP_COMMIT();
    }

    __syncthreads();
    float* red = (float*)RAWB;
    if (kh == 1) {
        float* p = red + (wq * 32 + lane) * 16;
#pragma unroll
        for (int j = 0; j < 4; j++)
#pragma unroll
            for (int e = 0; e < 4; e++) p[j * 4 + e] = acc[j][e];
    }
    __syncthreads();
    if (kh == 0) {
        const float* p = red + (wq * 32 + lane) * 16;
#pragma unroll
        for (int j = 0; j < 4; j++)
#pragma unroll
            for (int e = 0; e < 4; e++) acc[j][e] += p[j * 4 + e];
        int node = gg * N_ + dc * 128 + m0c + wm + g;
#pragma unroll
        for (int j = 0; j < 4; j++) {
            int col = n0 + wn + j * 8 + tg * 2;
            float b0 = convb[col], b1 = convb[col + 1];
            *(__half2*)&g_m1h[(size_t)node * F_ + col] =
                __floats2half2_rn(fmaxf(acc[j][0] + b0, 0.f), fmaxf(acc[j][1] + b1, 0.f));
            *(__half2*)&g_m1h[(size_t)(node + 8) * F_ + col] =
                __floats2half2_rn(fmaxf(acc[j][2] + b0, 0.f), fmaxf(acc[j][3] + b1, 0.f));
        }
    }
}

// lin: 128 vblocks = (4 x, 32 y). block 32x64, 2 K-groups x 4 warps (16x32), K=512
__device__ void lin_body(int vb, int layer, const float* __restrict__ linb, unsigned char* RAW) {
    int m0 = (vb >> 2) * 32, n0 = (vb & 3) * 64;
    int t = threadIdx.x, lane = t & 31, warp = t >> 5;
    int kh = warp >> 2, wq = warp & 3;
    int wm = (wq >> 1) * 16, wn = (wq & 1) * 32;
    int g = lane >> 2, tg = lane & 3;
    const __half* lwp = g_lwh + (size_t)layer * F_ * 2 * F_;

    auto stA = [&](int s, int h) { return (__half*)(RAW + s * 15360 + h * 2560); };
    auto stB = [&](int s, int h) { return (__half*)(RAW + s * 15360 + 5120 + h * 5120); };
    auto loadst = [&](int s, int k0) {
        {
            int h = t >> 7, rr = (t >> 2) & 31, seg = t & 3;
            const __half* Ab = (k0 < F_) ? &g_xh[(m0 + rr) * F_ + k0 + h * 32 + seg * 8]
                                         : &g_m1h[(m0 + rr) * F_ + (k0 - F_) + h * 32 + seg * 8];
            cpa16h(stA(s, h) + rr * (KW * 2) + seg * 8, Ab);
        }
#pragma unroll
        for (int u = 0; u < 2; u++) {
            int idx = t + u * 256;
            int h = idx >> 8, rr = (idx >> 2) & 63, seg = idx & 3;
            cpa16h(stB(s, h) + rr * (KW * 2) + seg * 8,
                   &lwp[(size_t)(n0 + rr) * 512 + k0 + h * 32 + seg * 8]);
        }
        CP_COMMIT();
    };

    float acc[4][4] = {};
    loadst(0, 0);
    loadst(1, 64);
    for (int i = 0; i < 8; i++) {
        CP_WAIT1();
        __syncthreads();
        const unsigned* Aw = (const unsigned*)stA(i % 3, kh);
        const unsigned* Bw = (const unsigned*)stB(i % 3, kh);
#pragma unroll
        for (int ks = 0; ks < 2; ks++) {
            int kw = ks * 8;
            unsigned a[4];
            a[0] = Aw[(wm + g) * KW + kw + tg];
            a[1] = Aw[(wm + g + 8) * KW + kw + tg];
            a[2] = Aw[(wm + g) * KW + kw + tg + 4];
            a[3] = Aw[(wm + g + 8) * KW + kw + tg + 4];
#pragma unroll
            for (int j = 0; j < 4; j++) {
                unsigned b[2];
                b[0] = Bw[(wn + j * 8 + g) * KW + kw + tg];
                b[1] = Bw[(wn + j * 8 + g) * KW + kw + tg + 4];
                mma16(acc[j], a, b);
            }
        }
        if (i + 2 < 8) loadst((i + 2) % 3, (i + 2) * 64);
        else CP_COMMIT();
    }

    __syncthreads();
    float* red = (float*)RAW;
    if (kh == 1) {
        float* p = red + (wq * 32 + lane) * 16;
#pragma unroll
        for (int j = 0; j < 4; j++)
#pragma unroll
            for (int e = 0; e < 4; e++) p[j * 4 + e] = acc[j][e];
    }
    __syncthreads();
    if (kh == 0) {
        const float* p = red + (wq * 32 + lane) * 16;
#pragma unroll
        for (int j = 0; j < 4; j++)
#pragma unroll
            for (int e = 0; e < 4; e++) acc[j][e] += p[j * 4 + e];

        int row = m0 + wm + g;
        float s0[4], s1[4], q0[4], q1[4];
#pragma unroll
        for (int j = 0; j < 4; j++) {
            int col = n0 + wn + j * 8 + tg * 2;
            float b0 = linb[col], b1 = linb[col + 1];
            float v0 = acc[j][0] + b0, v1 = acc[j][1] + b1;
            float v2 = acc[j][2] + b0, v3 = acc[j][3] + b1;
            *(float2*)&g_msg2[(size_t)row * F_ + col] = make_float2(v0, v1);
            *(float2*)&g_msg2[(size_t)(row + 8) * F_ + col] = make_float2(v2, v3);
            s0[j] = v0 + v2; s1[j] = v1 + v3;
            q0[j] = v0 * v0 + v2 * v2; q1[j] = v1 * v1 + v3 * v3;
        }
#pragma unroll
        for (int o = 4; o < 32; o <<= 1)
#pragma unroll
            for (int j = 0; j < 4; j++) {
                s0[j] += __shfl_xor_sync(0xffffffffu, s0[j], o);
                s1[j] += __shfl_xor_sync(0xffffffffu, s1[j], o);
                q0[j] += __shfl_xor_sync(0xffffffffu, q0[j], o);
                q1[j] += __shfl_xor_sync(0xffffffffu, q1[j], o);
            }
        if (g == 0) {
#pragma unroll
            for (int j = 0; j < 4; j++) {
                int col = n0 + wn + j * 8 + tg * 2;
                atomicAdd(&g_sum[col], s0[j]);
                atomicAdd(&g_sum[col + 1], s1[j]);
                atomicAdd(&g_sum2[col], q0[j]);
                atomicAdd(&g_sum2[col + 1], q1[j]);
            }
        }
    }
}

__device__ void bn_body(int b, const float* __restrict__ bw, const float* __restrict__ bb) {
    int c = threadIdx.x;
    float mu = g_sum[c] * (1.0f / BN_);
    float var = g_sum2[c] * (1.0f / BN_) - mu * mu;
    float rstd = rsqrtf(var + 1e-5f);
    float w = bw[c], bi = bb[c];
#pragma unroll
    for (int j = 0; j < 8; j++) {
        int idx = (b * 8 + j) * F_ + c;
        float v = g_x[idx] + w * (g_msg2[idx] - mu) * rstd + bi;
        g_x[idx] = v;
        g_xh[idx] = __float2half_rn(v);
    }
    if (b < 16) {
        int zi = b * 256 + c;
        if (zi < 2048) g_qs[zi] = 0.f;
        else           g_ks[zi - 2048] = 0.f;
    }
}

// ---------------- the persistent kernel ----------------
__global__ __launch_bounds__(256) void fused_k(
    const float* __restrict__ d0, const float* __restrict__ d1,
    const float* __restrict__ cw, const float* __restrict__ cq,
    const float* __restrict__ ck, const float* __restrict__ cb,
    const float* __restrict__ lw, const float* __restrict__ lb,
    const float* __restrict__ bw, const float* __restrict__ bb,
    float* __restrict__ out)
{
    extern __shared__ __align__(16) unsigned char RAW[];
    int b = blockIdx.x, t = threadIdx.x;

    // phase 0: prep (2176 vblocks = 17 per block)
    for (int j = 0; j < 17; j++) {
        prep_body(j * GRID + b, RAW, d0, d1, cw, lw);
        __syncthreads();
    }
    gbar(0);

#pragma unroll 1
    for (int layer = 0; layer < L_; layer++) {
        gemm_body(b, layer, cq + layer * F_, ck + layer * F_, RAW);
        gbar(layer * 4 + 1);
        attn_body(b, cb + layer * F_, RAW);
        gbar(layer * 4 + 2);
        lin_body(b, layer, lb + layer * F_, RAW);
        gbar(layer * 4 + 3);
        bn_body(b, bw + layer * F_, bb + layer * F_);
        gbar(layer * 4 + 4);
    }

    // unpack: 8 rows per block
#pragma unroll
    for (int j = 0; j < 8; j++) {
        int row = b * 8 + j;
        int bb2 = row >> 8, n = row & 255;
        float v = g_x[(bb2 * N_ + n) * F_ + t];
        if (n < N0_) out[(bb2 * F_ + t) * N0_ + n] = v;
        else         out[B_ * F_ * N0_ + (bb2 * F_ + t) * N0_ + (n - N0_)] = v;
    }

    // reset barrier state: last block to finish zeroes counters
    __syncthreads();
    if (t == 0) {
        unsigned prev;
        asm volatile("atom.add.release.gpu.u32 %0, [%1], 1;"
                     : "=r"(prev) : "l"(&g_donec) : "memory");
        if (prev == GRID - 1) {
            for (int i = 0; i < 16; i++) g_barc[i] = 0;
            g_donec = 0;
        }
    }
}

// ---------------- host ----------------
extern "C" void kernel_launch(void* const* d_in, const int* in_sizes, int n_in,
                              void* d_out, int out_size) {
    const float* desc0  = (const float*)d_in[0];
    const float* desc1  = (const float*)d_in[1];
    const float* conv_w = (const float*)d_in[2];
    const float* conv_q = (const float*)d_in[3];
    const float* conv_k = (const float*)d_in[4];
    const float* conv_b = (const float*)d_in[5];
    const float* lin_w  = (const float*)d_in[6];
    const float* lin_b  = (const float*)d_in[7];
    const float* bn_w   = (const float*)d_in[8];
    const float* bn_b   = (const float*)d_in[9];
    float* out = (float*)d_out;

    cudaFuncSetAttribute(fused_k, cudaFuncAttributeMaxDynamicSharedMemorySize, 61440);

    fused_k<<<GRID, 256, 61440>>>(desc0, desc1, conv_w, conv_q, conv_k, conv_b,
                                  lin_w, lin_b, bn_w, bn_b, out);
}

// round 17
// speedup vs baseline: 1.1839x; 1.1839x over previous
#include <cuda_runtime.h>
#include <cuda_fp16.h>
#include <math.h>

// ---------------- problem constants ----------------
#define B_   4
#define F_   256
#define N0_  128
#define N_   256
#define BN_  1024
#define L_   3

#define KW  20     // 32-bit words per 32-half smem row (16 data + 4 pad)
#define ALW 132    // 32-bit words per 256-half alpha row

// ---------------- scratch ----------------
__device__ float  g_x[BN_ * F_];
__device__ __half g_xh[BN_ * F_];
__device__ __half g_Hh[2 * F_ * BN_];     // H transposed: [r][e][node]
__device__ __half g_Wh[L_ * 2 * F_ * F_]; // conv W transposed
__device__ __half g_lwh[L_ * F_ * 2 * F_];
__device__ __half g_m1h[BN_ * F_];
__device__ float  g_msg2[BN_ * F_];
__device__ float  g_qs[2 * BN_], g_ks[2 * BN_];
__device__ float  g_sum[F_], g_sum2[F_];

// ---------------- helpers ----------------
__device__ __forceinline__ void mma16(float* d, const unsigned* a, const unsigned* b) {
    asm volatile(
        "mma.sync.aligned.m16n8k16.row.col.f32.f16.f16.f32 "
        "{%0,%1,%2,%3},{%4,%5,%6,%7},{%8,%9},{%0,%1,%2,%3};\n"
        : "+f"(d[0]), "+f"(d[1]), "+f"(d[2]), "+f"(d[3])
        : "r"(a[0]), "r"(a[1]), "r"(a[2]), "r"(a[3]), "r"(b[0]), "r"(b[1]));
}

__device__ __forceinline__ void cpa16h(__half* s, const __half* g) {
    unsigned ss = (unsigned)__cvta_generic_to_shared(s);
    asm volatile("cp.async.cg.shared.global [%0], [%1], 16;\n" :: "r"(ss), "l"(g));
}
#define CP_COMMIT() asm volatile("cp.async.commit_group;\n")
#define CP_WAIT1()  asm volatile("cp.async.wait_group 1;\n")

// ---------------- prep: pack + zero + round/transpose weights ----------------
__global__ void prep_kernel(const float* __restrict__ d0, const float* __restrict__ d1,
                            const float* __restrict__ cw, const float* __restrict__ lw) {
    __shared__ float s[32][33];
    int bid = blockIdx.x, t = threadIdx.x;
    if (bid < 1024) {
        int b = bid >> 8, n = bid & 255;
        float v = (n < N0_) ? d0[(b * F_ + t) * N0_ + n]
                            : d1[(b * F_ + t) * N0_ + (n - N0_)];
        int idx = (b * N_ + n) * F_ + t;
        g_x[idx] = v;
        g_xh[idx] = __float2half_rn(v);
        if (bid < 18) {
            int zi = bid * 256 + t;
            if (zi < 2048)       g_qs[zi] = 0.f;
            else if (zi < 4096)  g_ks[zi - 2048] = 0.f;
            else if (zi < 4352)  g_sum[zi - 4096] = 0.f;
            else                 g_sum2[zi - 4352] = 0.f;
        }
    } else if (bid < 1408) {
        int tt = bid - 1024, mat = tt >> 6, tile = tt & 63;
        int fr = (tile >> 3) * 32, ec = (tile & 7) * 32;
        int tx = t & 31, ty = t >> 5;
        for (int i = ty; i < 32; i += 8) s[i][tx] = cw[(mat * F_ + fr + i) * F_ + ec + tx];
        __syncthreads();
        for (int i = ty; i < 32; i += 8)
            g_Wh[((size_t)mat * F_ + ec + i) * F_ + fr + tx] = __float2half_rn(s[tx][i]);
    } else {
        size_t i0 = (size_t)(bid - 1408) * 512 + t;
        g_lwh[i0] = __float2half_rn(lw[i0]);
        g_lwh[i0 + 256] = __float2half_rn(lw[i0 + 256]);
    }
}

// ---------------- gemm_H: H[r]^T = (x@W[r])^T + fused q/k scores ----------------
// grid (4,16,2) x 512: block 64x64, 2 K-groups x 8 warps (16x32 tiles), BK=64/stage
__global__ __launch_bounds__(512) void gemm_H_k(int layer, const float* __restrict__ q,
                                                const float* __restrict__ kvec) {
    extern __shared__ __align__(16) unsigned char RAW[];
    int r = blockIdx.z;
    int m0 = blockIdx.y * 64, n0 = blockIdx.x * 64;
    int t = threadIdx.x, lane = t & 31, warp = t >> 5;
    int kh = warp >> 3, wq = warp & 7;
    int wm = (wq >> 1) * 16, wn = (wq & 1) * 32;
    int g = lane >> 2, tg = lane & 3;
    const __half* Wp = g_Wh + (size_t)(layer * 2 + r) * F_ * F_;

    if (blockIdx.x == 0 && blockIdx.y == 0 && blockIdx.z == 0) {
        for (int i = t; i < F_; i += 512) { g_sum[i] = 0.f; g_sum2[i] = 0.f; }
    }

    auto stA = [&](int s, int h) { return (__half*)(RAW + s * 20480 + h * 5120); };
    auto stB = [&](int s, int h) { return (__half*)(RAW + s * 20480 + 10240 + h * 5120); };
    auto loadst = [&](int s, int k0) {
        int h = t >> 8, rr = (t >> 2) & 63, seg = t & 3;
        cpa16h(stA(s, h) + rr * (KW * 2) + seg * 8, &g_xh[(m0 + rr) * F_ + k0 + h * 32 + seg * 8]);
        cpa16h(stB(s, h) + rr * (KW * 2) + seg * 8, &Wp[(n0 + rr) * F_ + k0 + h * 32 + seg * 8]);
        CP_COMMIT();
    };

    float acc[4][4] = {};
    loadst(0, 0);
    loadst(1, 64);
    for (int i = 0; i < 4; i++) {
        CP_WAIT1();
        __syncthreads();
        const unsigned* Aw = (const unsigned*)stA(i % 3, kh);
        const unsigned* Bw = (const unsigned*)stB(i % 3, kh);
#pragma unroll
        for (int ks = 0; ks < 2; ks++) {
            int kw = ks * 8;
            unsigned a[4];
            a[0] = Aw[(wm + g) * KW + kw + tg];
            a[1] = Aw[(wm + g + 8) * KW + kw + tg];
            a[2] = Aw[(wm + g) * KW + kw + tg + 4];
            a[3] = Aw[(wm + g + 8) * KW + kw + tg + 4];
#pragma unroll
            for (int j = 0; j < 4; j++) {
                unsigned b[2];
                b[0] = Bw[(wn + j * 8 + g) * KW + kw + tg];
                b[1] = Bw[(wn + j * 8 + g) * KW + kw + tg + 4];
                mma16(acc[j], a, b);
            }
        }
        if (i + 2 < 4) loadst((i + 2) % 3, (i + 2) * 64);
        else CP_COMMIT();
    }

    // split-K reduction: group0 += group1 (deterministic)
    __syncthreads();
    float* red = (float*)RAW;
    if (kh == 1) {
        float* p = red + (wq * 32 + lane) * 16;
#pragma unroll
        for (int j = 0; j < 4; j++)
#pragma unroll
            for (int e = 0; e < 4; e++) p[j * 4 + e] = acc[j][e];
    }
    __syncthreads();
    if (kh == 0) {
        const float* p = red + (wq * 32 + lane) * 16;
#pragma unroll
        for (int j = 0; j < 4; j++)
#pragma unroll
            for (int e = 0; e < 4; e++) acc[j][e] += p[j * 4 + e];

        // fused q/k partial dots over this block's 64 cols
        float qp0 = 0, qp1 = 0, kp0 = 0, kp1 = 0;
#pragma unroll
        for (int j = 0; j < 4; j++) {
            int col = n0 + wn + j * 8 + tg * 2;
            float2 qv = *(const float2*)&q[col];
            float2 kv = *(const float2*)&kvec[col];
            qp0 += acc[j][0] * qv.x + acc[j][1] * qv.y;
            qp1 += acc[j][2] * qv.x + acc[j][3] * qv.y;
            kp0 += acc[j][0] * kv.x + acc[j][1] * kv.y;
            kp1 += acc[j][2] * kv.x + acc[j][3] * kv.y;
        }
#pragma unroll
        for (int o = 1; o < 4; o <<= 1) {
            qp0 += __shfl_xor_sync(0xffffffffu, qp0, o);
            qp1 += __shfl_xor_sync(0xffffffffu, qp1, o);
            kp0 += __shfl_xor_sync(0xffffffffu, kp0, o);
            kp1 += __shfl_xor_sync(0xffffffffu, kp1, o);
        }
        if (tg == 0) {
            int row = m0 + wm + g;
            atomicAdd(&g_qs[r * BN_ + row], qp0);
            atomicAdd(&g_qs[r * BN_ + row + 8], qp1);
            atomicAdd(&g_ks[r * BN_ + row], kp0);
            atomicAdd(&g_ks[r * BN_ + row + 8], kp1);
        }
    }
    __syncthreads();
    // transposed H store via smem staging T[64 e][80]
    __half* T = (__half*)(RAW + 16384);
    if (kh == 0) {
#pragma unroll
        for (int j = 0; j < 4; j++) {
            int cl = wn + j * 8 + tg * 2, rl = wm + g;
            T[cl * 80 + rl] = __float2half_rn(acc[j][0]);
            T[(cl + 1) * 80 + rl] = __float2half_rn(acc[j][1]);
            T[cl * 80 + rl + 8] = __float2half_rn(acc[j][2]);
            T[(cl + 1) * 80 + rl + 8] = __float2half_rn(acc[j][3]);
        }
    }
    __syncthreads();
    size_t base = ((size_t)r * F_ + n0) * BN_ + m0;
    {
        int row = t >> 3, seg = t & 7;
        *(uint4*)&g_Hh[base + (size_t)row * BN_ + seg * 8] = *(const uint4*)&T[row * 80 + seg * 8];
    }
}

// ---------------- attn: fused softmax + aggregation + relu(+bias) ----------------
// grid (4,4,8) x 512: block 32x64, 2 K-groups x 8 warps (16x16 tiles)
__global__ __launch_bounds__(512) void attn_k(const float* __restrict__ convb) {
    int z = blockIdx.z, gg = z >> 1, dc = z & 1;
    int m0c = blockIdx.y * 32, n0 = blockIdx.x * 64;
    __shared__ __align__(16) __half AL[32 * 264];
    __shared__ __align__(16) unsigned char RAWB[3 * 10240];
    int t = threadIdx.x, lane = t & 31, warp = t >> 5;
    int kh = warp >> 3, wq = warp & 7;
    int wm = (wq >> 2) * 16, wn = (wq & 3) * 16;
    int g = lane >> 2, tg = lane & 3;

    auto stB = [&](int s, int h) { return (__half*)(RAWB + s * 10240 + h * 5120); };
    auto loadB = [&](int s, int k0) {
        int rel = (k0 >> 7) ^ dc;
        const __half* src = g_Hh + ((size_t)rel * F_ + n0) * BN_ + gg * N_ + k0;
        int h = t >> 8, rr = (t >> 2) & 63, seg = t & 3;
        cpa16h(stB(s, h) + rr * (KW * 2) + seg * 8, &src[(size_t)rr * BN_ + h * 32 + seg * 8]);
        CP_COMMIT();
    };
    loadB(0, 0);
    loadB(1, 64);

    // alpha: 16 warps x 2 rows
#pragma unroll
    for (int rr = 0; rr < 2; rr++) {
        int rl = warp * 2 + rr;
        int d = dc * 128 + m0c + rl;
        int nd = gg * N_ + d;
        float qs0 = g_qs[nd];
        float qs1 = g_qs[BN_ + nd];
        float l[8];
        float mx = -INFINITY;
#pragma unroll
        for (int j = 0; j < 8; j++) {
            int s = j * 32 + lane;
            int rel = (s >> 7) ^ dc;
            float ksv = g_ks[rel * BN_ + gg * N_ + s];
            float qv = rel ? qs1 : qs0;
            float v = qv + ksv;
            v = v >= 0.0f ? v : 0.2f * v;
            if (s == d) v = -INFINITY;
            l[j] = v;
            mx = fmaxf(mx, v);
        }
#pragma unroll
        for (int o = 16; o; o >>= 1) mx = fmaxf(mx, __shfl_xor_sync(0xffffffffu, mx, o));
        float sum = 0.0f;
#pragma unroll
        for (int j = 0; j < 8; j++) { l[j] = expf(l[j] - mx); sum += l[j]; }
#pragma unroll
        for (int o = 16; o; o >>= 1) sum += __shfl_xor_sync(0xffffffffu, sum, o);
        float inv = 1.0f / (sum + 1e-16f);
#pragma unroll
        for (int j = 0; j < 8; j++) AL[rl * 264 + j * 32 + lane] = __float2half_rn(l[j] * inv);
    }

    float acc[2][4] = {};
    const unsigned* ALw = (const unsigned*)AL;
    for (int i = 0; i < 4; i++) {
        CP_WAIT1();
        __syncthreads();
        const unsigned* Bw = (const unsigned*)stB(i % 3, kh);
#pragma unroll
        for (int ks = 0; ks < 2; ks++) {
            int kwA = i * 32 + kh * 16 + ks * 8, kwB = ks * 8;
            unsigned a[4];
            a[0] = ALw[(wm + g) * ALW + kwA + tg];
            a[1] = ALw[(wm + g + 8) * ALW + kwA + tg];
            a[2] = ALw[(wm + g) * ALW + kwA + tg + 4];
            a[3] = ALw[(wm + g + 8) * ALW + kwA + tg + 4];
#pragma unroll
            for (int j = 0; j < 2; j++) {
                unsigned b[2];
                b[0] = Bw[(wn + j * 8 + g) * KW + kwB + tg];
                b[1] = Bw[(wn + j * 8 + g) * KW + kwB + tg + 4];
                mma16(acc[j], a, b);
            }
        }
        if (i + 2 < 4) loadB((i + 2) % 3, (i + 2) * 64);
        else CP_COMMIT();
    }

    __syncthreads();
    float* red = (float*)RAWB;
    if (kh == 1) {
        float* p = red + (wq * 32 + lane) * 8;
#pragma unroll
        for (int j = 0; j < 2; j++)
#pragma unroll
            for (int e = 0; e < 4; e++) p[j * 4 + e] = acc[j][e];
    }
    __syncthreads();
    if (kh == 0) {
        const float* p = red + (wq * 32 + lane) * 8;
#pragma unroll
        for (int j = 0; j < 2; j++)
#pragma unroll
            for (int e = 0; e < 4; e++) acc[j][e] += p[j * 4 + e];
        int node = gg * N_ + dc * 128 + m0c + wm + g;
#pragma unroll
        for (int j = 0; j < 2; j++) {
            int col = n0 + wn + j * 8 + tg * 2;
            float b0 = convb[col], b1 = convb[col + 1];
            *(__half2*)&g_m1h[(size_t)node * F_ + col] =
                __floats2half2_rn(fmaxf(acc[j][0] + b0, 0.f), fmaxf(acc[j][1] + b1, 0.f));
            *(__half2*)&g_m1h[(size_t)(node + 8) * F_ + col] =
                __floats2half2_rn(fmaxf(acc[j][2] + b0, 0.f), fmaxf(acc[j][3] + b1, 0.f));
        }
    }
}

// ---------------- lin: msg2 = [x,msg1]@lin_w^T + b (fp32 out) + BN sums ----------------
// grid (4,32) x 512: block 32x64, 2 K-groups x 8 warps (16x16 tiles), K=512
__global__ __launch_bounds__(512) void lin_k(int layer, const float* __restrict__ linb) {
    int m0 = blockIdx.y * 32, n0 = blockIdx.x * 64;
    __shared__ __align__(16) unsigned char RAW[3 * 15360];
    int t = threadIdx.x, lane = t & 31, warp = t >> 5;
    int kh = warp >> 3, wq = warp & 7;
    int wm = (wq >> 2) * 16, wn = (wq & 3) * 16;
    int g = lane >> 2, tg = lane & 3;
    const __half* lwp = g_lwh + (size_t)layer * F_ * 2 * F_;

    auto stA = [&](int s, int h) { return (__half*)(RAW + s * 15360 + h * 2560); };
    auto stB = [&](int s, int h) { return (__half*)(RAW + s * 15360 + 5120 + h * 5120); };
    auto loadst = [&](int s, int k0) {
        if (t < 256) {
            int h = t >> 7, rr = (t >> 2) & 31, seg = t & 3;
            const __half* Ab = (k0 < F_) ? &g_xh[(m0 + rr) * F_ + k0 + h * 32 + seg * 8]
                                         : &g_m1h[(m0 + rr) * F_ + (k0 - F_) + h * 32 + seg * 8];
            cpa16h(stA(s, h) + rr * (KW * 2) + seg * 8, Ab);
        }
        {
            int h = t >> 8, rr = (t >> 2) & 63, seg = t & 3;
            cpa16h(stB(s, h) + rr * (KW * 2) + seg * 8,
                   &lwp[(size_t)(n0 + rr) * 512 + k0 + h * 32 + seg * 8]);
        }
        CP_COMMIT();
    };

    float acc[2][4] = {};
    loadst(0, 0);
    loadst(1, 64);
    for (int i = 0; i < 8; i++) {
        CP_WAIT1();
        __syncthreads();
        const unsigned* Aw = (const unsigned*)stA(i % 3, kh);
        const unsigned* Bw = (const unsigned*)stB(i % 3, kh);
#pragma unroll
        for (int ks = 0; ks < 2; ks++) {
            int kw = ks * 8;
            unsigned a[4];
            a[0] = Aw[(wm + g) * KW + kw + tg];
            a[1] = Aw[(wm + g + 8) * KW + kw + tg];
            a[2] = Aw[(wm + g) * KW + kw + tg + 4];
            a[3] = Aw[(wm + g + 8) * KW + kw + tg + 4];
#pragma unroll
            for (int j = 0; j < 2; j++) {
                unsigned b[2];
                b[0] = Bw[(wn + j * 8 + g) * KW + kw + tg];
                b[1] = Bw[(wn + j * 8 + g) * KW + kw + tg + 4];
                mma16(acc[j], a, b);
            }
        }
        if (i + 2 < 8) loadst((i + 2) % 3, (i + 2) * 64);
        else CP_COMMIT();
    }

    __syncthreads();
    float* red = (float*)RAW;
    if (kh == 1) {
        float* p = red + (wq * 32 + lane) * 8;
#pragma unroll
        for (int j = 0; j < 2; j++)
#pragma unroll
            for (int e = 0; e < 4; e++) p[j * 4 + e] = acc[j][e];
    }
    __syncthreads();
    if (kh == 0) {
        const float* p = red + (wq * 32 + lane) * 8;
#pragma unroll
        for (int j = 0; j < 2; j++)
#pragma unroll
            for (int e = 0; e < 4; e++) acc[j][e] += p[j * 4 + e];

        int row = m0 + wm + g;
        float s0[2], s1[2], q0[2], q1[2];
#pragma unroll
        for (int j = 0; j < 2; j++) {
            int col = n0 + wn + j * 8 + tg * 2;
            float b0 = linb[col], b1 = linb[col + 1];
            float v0 = acc[j][0] + b0, v1 = acc[j][1] + b1;
            float v2 = acc[j][2] + b0, v3 = acc[j][3] + b1;
            *(float2*)&g_msg2[(size_t)row * F_ + col] = make_float2(v0, v1);
            *(float2*)&g_msg2[(size_t)(row + 8) * F_ + col] = make_float2(v2, v3);
            s0[j] = v0 + v2; s1[j] = v1 + v3;
            q0[j] = v0 * v0 + v2 * v2; q1[j] = v1 * v1 + v3 * v3;
        }
#pragma unroll
        for (int o = 4; o < 32; o <<= 1)
#pragma unroll
            for (int j = 0; j < 2; j++) {
                s0[j] += __shfl_xor_sync(0xffffffffu, s0[j], o);
                s1[j] += __shfl_xor_sync(0xffffffffu, s1[j], o);
                q0[j] += __shfl_xor_sync(0xffffffffu, q0[j], o);
                q1[j] += __shfl_xor_sync(0xffffffffu, q1[j], o);
            }
        if (g == 0) {
#pragma unroll
            for (int j = 0; j < 2; j++) {
                int col = n0 + wn + j * 8 + tg * 2;
                atomicAdd(&g_sum[col], s0[j]);
                atomicAdd(&g_sum[col + 1], s1[j]);
                atomicAdd(&g_sum2[col], q0[j]);
                atomicAdd(&g_sum2[col + 1], q1[j]);
            }
        }
    }
}

// ---------------- batchnorm apply (mu/rstd inline) + residual ----------------
__global__ void bn_apply(const float* __restrict__ bw, const float* __restrict__ bb) {
    int c = threadIdx.x;
    float mu = g_sum[c] * (1.0f / BN_);
    float var = g_sum2[c] * (1.0f / BN_) - mu * mu;
    float rstd = rsqrtf(var + 1e-5f);
    int idx = blockIdx.x * F_ + c;
    float v = g_x[idx] + bw[c] * (g_msg2[idx] - mu) * rstd + bb[c];
    g_x[idx] = v;
    g_xh[idx] = __float2half_rn(v);
    if (blockIdx.x < 16) {
        int zi = blockIdx.x * 256 + c;
        if (zi < 2048) g_qs[zi] = 0.f;
        else           g_ks[zi - 2048] = 0.f;
    }
}

// ---------------- unpack ----------------
__global__ void unpack_kernel(float* __restrict__ out) {
    int b = blockIdx.x >> 8;
    int n = blockIdx.x & 255;
    int f = threadIdx.x;
    float v = g_x[(b * N_ + n) * F_ + f];
    if (n < N0_) out[(b * F_ + f) * N0_ + n] = v;
    else         out[B_ * F_ * N0_ + (b * F_ + f) * N0_ + (n - N0_)] = v;
}

// ---------------- host ----------------
extern "C" void kernel_launch(void* const* d_in, const int* in_sizes, int n_in,
                              void* d_out, int out_size) {
    const float* desc0  = (const float*)d_in[0];
    const float* desc1  = (const float*)d_in[1];
    const float* conv_w = (const float*)d_in[2];
    const float* conv_q = (const float*)d_in[3];
    const float* conv_k = (const float*)d_in[4];
    const float* conv_b = (const float*)d_in[5];
    const float* lin_w  = (const float*)d_in[6];
    const float* lin_b  = (const float*)d_in[7];
    const float* bn_w   = (const float*)d_in[8];
    const float* bn_b   = (const float*)d_in[9];
    float* out = (float*)d_out;

    cudaFuncSetAttribute(gemm_H_k, cudaFuncAttributeMaxDynamicSharedMemorySize, 61440);

    prep_kernel<<<2176, 256>>>(desc0, desc1, conv_w, lin_w);

    for (int i = 0; i < L_; i++) {
        gemm_H_k<<<dim3(4, 16, 2), 512, 61440>>>(i, conv_q + i * F_, conv_k + i * F_);
        attn_k<<<dim3(4, 4, 8), 512>>>(conv_b + i * F_);
        lin_k<<<dim3(4, 32), 512>>>(i, lin_b + i * F_);
        bn_apply<<<BN_, F_>>>(bn_w + i * F_, bn_b + i * F_);
    }

    unpack_kernel<<<BN_, F_>>>(out);
}